// round 2
// baseline (speedup 1.0000x reference)
#include <cuda_runtime.h>
#include <math.h>

// Problem constants
#define NN 50000
#define EE 800000
#define HH 64
#define FF 64
#define CC 10
#define KK 4
#define LL 3
#define NB_BATCH 256
#define SPAD 68   // padded smem row stride (floats), 16B-aligned, avoids bank conflicts

// ---------------- device scratch (static, no allocation) ----------------
__device__ float g_Z[NN * HH];        // encoder output Z
__device__ float g_agg[NN * HH];      // GIN aggregation buffer
__device__ float g_hcur[NN * HH];     // per-expert node features (cl GIN)
__device__ float g_AB[NN * 2 * HH];   // per-expert edge-MLP precompute: cols 0..63 = Z@W1_top, 64..127 = Z@W1_bot
__device__ float g_ew[EE];            // per-expert edge weights
__device__ float g_poolZ[NB_BATCH * HH];
__device__ float g_poolS[KK * NB_BATCH * HH];
__device__ int   g_cnt[NB_BATCH];

__device__ __forceinline__ void red_add_f4(float4* p, float4 v) {
    asm volatile("red.global.add.v4.f32 [%0], {%1,%2,%3,%4};"
                 :: "l"(p), "f"(v.x), "f"(v.y), "f"(v.z), "f"(v.w) : "memory");
}
__device__ __forceinline__ float sigmoidf_(float v) { return 1.0f / (1.0f + expf(-v)); }

// ---------------- gather + scatter-add (GIN aggregation) ----------------
// 8 threads per edge, 2 float4 each. Optional per-edge weight.
__global__ __launch_bounds__(256) void scatter_kernel(
    const float* __restrict__ h, const int* __restrict__ src,
    const int* __restrict__ dst, const float* __restrict__ ew)
{
    int idx = blockIdx.x * 256 + threadIdx.x;
    int e = idx >> 3, lane = idx & 7;
    int s = src[e], d = dst[e];
    const float4* hs = (const float4*)(h + (size_t)s * HH) + lane * 2;
    float4 v0 = hs[0], v1 = hs[1];
    if (ew) {
        float w = ew[e];
        v0.x *= w; v0.y *= w; v0.z *= w; v0.w *= w;
        v1.x *= w; v1.y *= w; v1.z *= w; v1.w *= w;
    }
    float4* ad = (float4*)(g_agg + (size_t)d * HH) + lane * 2;
    red_add_f4(ad, v0);
    red_add_f4(ad + 1, v1);
}

// ---------------- fused 2-layer GIN MLP: h' = relu(relu(((1+eps)h+agg)W1+b1)W2+b2) --------
__global__ __launch_bounds__(256) void ginmlp_kernel(
    const float* __restrict__ hin, const float* __restrict__ eps_ptr, int lidx,
    const float* __restrict__ W1, const float* __restrict__ b1,
    const float* __restrict__ W2, const float* __restrict__ b2,
    float* __restrict__ hout)
{
    __shared__ __align__(16) float Ts[64 * SPAD];   // transposed activations: Ts[k][row]
    __shared__ __align__(16) float Ws[64 * SPAD];   // weights: Ws[k][col]
    __shared__ float bsh[64];
    __shared__ float bsh2[64];
    int tid = threadIdx.x;
    int r0 = blockIdx.x * 64;
    float epsv = 1.0f + eps_ptr[lidx];
    {   // load t = (1+eps)*h + agg, transposed into Ts
        int row = tid >> 2, part = tid & 3;
        int gr = r0 + row;
        #pragma unroll
        for (int q = 0; q < 4; q++) {
            float4 v = make_float4(0.f, 0.f, 0.f, 0.f);
            if (gr < NN) {
                v = *((const float4*)(hin + (size_t)gr * HH + part * 16 + q * 4));
                float4 a = *((const float4*)(g_agg + (size_t)gr * HH + part * 16 + q * 4));
                v.x = fmaf(v.x, epsv, a.x); v.y = fmaf(v.y, epsv, a.y);
                v.z = fmaf(v.z, epsv, a.z); v.w = fmaf(v.w, epsv, a.w);
            }
            int k = part * 16 + q * 4;
            Ts[(k+0)*SPAD + row] = v.x; Ts[(k+1)*SPAD + row] = v.y;
            Ts[(k+2)*SPAD + row] = v.z; Ts[(k+3)*SPAD + row] = v.w;
        }
    }
    for (int i = tid; i < 1024; i += 256) {
        float4 w = ((const float4*)W1)[i];
        *((float4*)&Ws[(i >> 4) * SPAD + (i & 15) * 4]) = w;
    }
    if (tid < 64) { bsh[tid] = b1[tid]; bsh2[tid] = b2[tid]; }
    __syncthreads();

    int tx = tid & 15, ty = tid >> 4;
    float acc[4][4];
    #pragma unroll
    for (int i = 0; i < 4; i++)
        #pragma unroll
        for (int j = 0; j < 4; j++) acc[i][j] = 0.f;
    #pragma unroll
    for (int k = 0; k < 64; k++) {
        float4 a4 = *((const float4*)&Ts[k * SPAD + ty * 4]);
        float4 b4 = *((const float4*)&Ws[k * SPAD + tx * 4]);
        float av[4] = {a4.x, a4.y, a4.z, a4.w}, bv[4] = {b4.x, b4.y, b4.z, b4.w};
        #pragma unroll
        for (int i = 0; i < 4; i++)
            #pragma unroll
            for (int j = 0; j < 4; j++) acc[i][j] = fmaf(av[i], bv[j], acc[i][j]);
    }
    __syncthreads();
    // h1 = relu(acc + b1), store transposed back into Ts; load W2
    #pragma unroll
    for (int i = 0; i < 4; i++)
        #pragma unroll
        for (int j = 0; j < 4; j++) {
            float h = fmaxf(acc[i][j] + bsh[tx*4+j], 0.f);
            Ts[(tx*4+j) * SPAD + ty*4 + i] = h;
        }
    for (int i = tid; i < 1024; i += 256) {
        float4 w = ((const float4*)W2)[i];
        *((float4*)&Ws[(i >> 4) * SPAD + (i & 15) * 4]) = w;
    }
    __syncthreads();
    #pragma unroll
    for (int i = 0; i < 4; i++)
        #pragma unroll
        for (int j = 0; j < 4; j++) acc[i][j] = 0.f;
    #pragma unroll
    for (int k = 0; k < 64; k++) {
        float4 a4 = *((const float4*)&Ts[k * SPAD + ty * 4]);
        float4 b4 = *((const float4*)&Ws[k * SPAD + tx * 4]);
        float av[4] = {a4.x, a4.y, a4.z, a4.w}, bv[4] = {b4.x, b4.y, b4.z, b4.w};
        #pragma unroll
        for (int i = 0; i < 4; i++)
            #pragma unroll
            for (int j = 0; j < 4; j++) acc[i][j] = fmaf(av[i], bv[j], acc[i][j]);
    }
    #pragma unroll
    for (int i = 0; i < 4; i++) {
        int gr = r0 + ty * 4 + i;
        if (gr < NN) {
            float4 o;
            o.x = fmaxf(acc[i][0] + bsh2[tx*4+0], 0.f);
            o.y = fmaxf(acc[i][1] + bsh2[tx*4+1], 0.f);
            o.z = fmaxf(acc[i][2] + bsh2[tx*4+2], 0.f);
            o.w = fmaxf(acc[i][3] + bsh2[tx*4+3], 0.f);
            *((float4*)(hout + (size_t)gr * HH + tx * 4)) = o;
        }
    }
}

// ---------------- AB precompute for edge masks: g_AB[n] = [Z@W1[0:64] | Z@W1[64:128]] ------
__global__ __launch_bounds__(256) void gemmAB_kernel(
    const float* __restrict__ Z, const float* __restrict__ W1)
{
    __shared__ __align__(16) float Ts[64 * SPAD];
    __shared__ __align__(16) float Ws[64 * SPAD];
    int tid = threadIdx.x, r0 = blockIdx.x * 64;
    {
        int row = tid >> 2, part = tid & 3, gr = r0 + row;
        #pragma unroll
        for (int q = 0; q < 4; q++) {
            float4 v = make_float4(0.f, 0.f, 0.f, 0.f);
            if (gr < NN) v = *((const float4*)(Z + (size_t)gr * HH + part * 16 + q * 4));
            int k = part * 16 + q * 4;
            Ts[(k+0)*SPAD + row] = v.x; Ts[(k+1)*SPAD + row] = v.y;
            Ts[(k+2)*SPAD + row] = v.z; Ts[(k+3)*SPAD + row] = v.w;
        }
    }
    int tx = tid & 15, ty = tid >> 4;
    #pragma unroll
    for (int half = 0; half < 2; half++) {
        for (int i = tid; i < 1024; i += 256) {
            float4 w = ((const float4*)(W1 + half * 64 * 64))[i];
            *((float4*)&Ws[(i >> 4) * SPAD + (i & 15) * 4]) = w;
        }
        __syncthreads();
        float acc[4][4];
        #pragma unroll
        for (int i = 0; i < 4; i++)
            #pragma unroll
            for (int j = 0; j < 4; j++) acc[i][j] = 0.f;
        #pragma unroll
        for (int k = 0; k < 64; k++) {
            float4 a4 = *((const float4*)&Ts[k * SPAD + ty * 4]);
            float4 b4 = *((const float4*)&Ws[k * SPAD + tx * 4]);
            float av[4] = {a4.x, a4.y, a4.z, a4.w}, bv[4] = {b4.x, b4.y, b4.z, b4.w};
            #pragma unroll
            for (int i = 0; i < 4; i++)
                #pragma unroll
                for (int j = 0; j < 4; j++) acc[i][j] = fmaf(av[i], bv[j], acc[i][j]);
        }
        #pragma unroll
        for (int i = 0; i < 4; i++) {
            int gr = r0 + ty * 4 + i;
            if (gr < NN) {
                float4 o = make_float4(acc[i][0], acc[i][1], acc[i][2], acc[i][3]);
                *((float4*)(g_AB + (size_t)gr * 128 + half * 64 + tx * 4)) = o;
            }
        }
        __syncthreads();
    }
}

// ---------------- node-mask MLP: sigmoid(relu(Z@W1+b1) . W2 + b2) -> out[n*K] -------------
__global__ __launch_bounds__(256) void nm_kernel(
    const float* __restrict__ Z,
    const float* __restrict__ W1, const float* __restrict__ b1,
    const float* __restrict__ W2, const float* __restrict__ b2,
    float* __restrict__ outp)   // already offset by k; stride KK per node
{
    __shared__ __align__(16) float Ts[64 * SPAD];
    __shared__ __align__(16) float Ws[64 * SPAD];
    __shared__ float bsh[64];
    __shared__ float w2s[64];
    int tid = threadIdx.x, r0 = blockIdx.x * 64;
    {
        int row = tid >> 2, part = tid & 3, gr = r0 + row;
        #pragma unroll
        for (int q = 0; q < 4; q++) {
            float4 v = make_float4(0.f, 0.f, 0.f, 0.f);
            if (gr < NN) v = *((const float4*)(Z + (size_t)gr * HH + part * 16 + q * 4));
            int k = part * 16 + q * 4;
            Ts[(k+0)*SPAD + row] = v.x; Ts[(k+1)*SPAD + row] = v.y;
            Ts[(k+2)*SPAD + row] = v.z; Ts[(k+3)*SPAD + row] = v.w;
        }
    }
    for (int i = tid; i < 1024; i += 256) {
        float4 w = ((const float4*)W1)[i];
        *((float4*)&Ws[(i >> 4) * SPAD + (i & 15) * 4]) = w;
    }
    if (tid < 64) { bsh[tid] = b1[tid]; w2s[tid] = W2[tid]; }
    __syncthreads();
    int tx = tid & 15, ty = tid >> 4;
    float acc[4][4];
    #pragma unroll
    for (int i = 0; i < 4; i++)
        #pragma unroll
        for (int j = 0; j < 4; j++) acc[i][j] = 0.f;
    #pragma unroll
    for (int k = 0; k < 64; k++) {
        float4 a4 = *((const float4*)&Ts[k * SPAD + ty * 4]);
        float4 b4 = *((const float4*)&Ws[k * SPAD + tx * 4]);
        float av[4] = {a4.x, a4.y, a4.z, a4.w}, bv[4] = {b4.x, b4.y, b4.z, b4.w};
        #pragma unroll
        for (int i = 0; i < 4; i++)
            #pragma unroll
            for (int j = 0; j < 4; j++) acc[i][j] = fmaf(av[i], bv[j], acc[i][j]);
    }
    float b2v = b2[0];
    #pragma unroll
    for (int i = 0; i < 4; i++) {
        float p = 0.f;
        #pragma unroll
        for (int j = 0; j < 4; j++)
            p += fmaxf(acc[i][j] + bsh[tx*4+j], 0.f) * w2s[tx*4+j];
        #pragma unroll
        for (int off = 8; off > 0; off >>= 1)
            p += __shfl_down_sync(0xffffffffu, p, off, 16);
        if (tx == 0) {
            int gr = r0 + ty * 4 + i;
            if (gr < NN) outp[(size_t)gr * KK] = sigmoidf_(p + b2v);
        }
    }
}

// ---------------- feature-mask MLP + masked_x -> g_hcur ----------------
__global__ __launch_bounds__(256) void fm_kernel(
    const float* __restrict__ Z, const float* __restrict__ x,
    const float* __restrict__ nm_k,   // out_nm + k, stride KK per node
    const float* __restrict__ W1, const float* __restrict__ b1,
    const float* __restrict__ W2, const float* __restrict__ b2,
    float* __restrict__ out_fm_k)     // out_fm + k*FF, row stride KK*FF
{
    __shared__ __align__(16) float Ts[64 * SPAD];
    __shared__ __align__(16) float Ws[64 * SPAD];
    __shared__ float bsh[64];
    __shared__ float bsh2[64];
    __shared__ float nmv[64];
    int tid = threadIdx.x, r0 = blockIdx.x * 64;
    {
        int row = tid >> 2, part = tid & 3, gr = r0 + row;
        #pragma unroll
        for (int q = 0; q < 4; q++) {
            float4 v = make_float4(0.f, 0.f, 0.f, 0.f);
            if (gr < NN) v = *((const float4*)(Z + (size_t)gr * HH + part * 16 + q * 4));
            int k = part * 16 + q * 4;
            Ts[(k+0)*SPAD + row] = v.x; Ts[(k+1)*SPAD + row] = v.y;
            Ts[(k+2)*SPAD + row] = v.z; Ts[(k+3)*SPAD + row] = v.w;
        }
    }
    for (int i = tid; i < 1024; i += 256) {
        float4 w = ((const float4*)W1)[i];
        *((float4*)&Ws[(i >> 4) * SPAD + (i & 15) * 4]) = w;
    }
    if (tid < 64) {
        bsh[tid] = b1[tid]; bsh2[tid] = b2[tid];
        int gr = r0 + tid;
        nmv[tid] = (gr < NN) ? nm_k[(size_t)gr * KK] : 0.f;
    }
    __syncthreads();
    int tx = tid & 15, ty = tid >> 4;
    float acc[4][4];
    #pragma unroll
    for (int i = 0; i < 4; i++)
        #pragma unroll
        for (int j = 0; j < 4; j++) acc[i][j] = 0.f;
    #pragma unroll
    for (int k = 0; k < 64; k++) {
        float4 a4 = *((const float4*)&Ts[k * SPAD + ty * 4]);
        float4 b4 = *((const float4*)&Ws[k * SPAD + tx * 4]);
        float av[4] = {a4.x, a4.y, a4.z, a4.w}, bv[4] = {b4.x, b4.y, b4.z, b4.w};
        #pragma unroll
        for (int i = 0; i < 4; i++)
            #pragma unroll
            for (int j = 0; j < 4; j++) acc[i][j] = fmaf(av[i], bv[j], acc[i][j]);
    }
    __syncthreads();
    #pragma unroll
    for (int i = 0; i < 4; i++)
        #pragma unroll
        for (int j = 0; j < 4; j++) {
            float h = fmaxf(acc[i][j] + bsh[tx*4+j], 0.f);
            Ts[(tx*4+j) * SPAD + ty*4 + i] = h;
        }
    for (int i = tid; i < 1024; i += 256) {
        float4 w = ((const float4*)W2)[i];
        *((float4*)&Ws[(i >> 4) * SPAD + (i & 15) * 4]) = w;
    }
    __syncthreads();
    #pragma unroll
    for (int i = 0; i < 4; i++)
        #pragma unroll
        for (int j = 0; j < 4; j++) acc[i][j] = 0.f;
    #pragma unroll
    for (int k = 0; k < 64; k++) {
        float4 a4 = *((const float4*)&Ts[k * SPAD + ty * 4]);
        float4 b4 = *((const float4*)&Ws[k * SPAD + tx * 4]);
        float av[4] = {a4.x, a4.y, a4.z, a4.w}, bv[4] = {b4.x, b4.y, b4.z, b4.w};
        #pragma unroll
        for (int i = 0; i < 4; i++)
            #pragma unroll
            for (int j = 0; j < 4; j++) acc[i][j] = fmaf(av[i], bv[j], acc[i][j]);
    }
    #pragma unroll
    for (int i = 0; i < 4; i++) {
        int gr = r0 + ty * 4 + i;
        if (gr < NN) {
            float nmu = nmv[ty*4 + i];
            float4 xr = *((const float4*)(x + (size_t)gr * FF + tx * 4));
            float4 sg;
            sg.x = sigmoidf_(acc[i][0] + bsh2[tx*4+0]);
            sg.y = sigmoidf_(acc[i][1] + bsh2[tx*4+1]);
            sg.z = sigmoidf_(acc[i][2] + bsh2[tx*4+2]);
            sg.w = sigmoidf_(acc[i][3] + bsh2[tx*4+3]);
            *((float4*)(out_fm_k + (size_t)gr * (KK * FF) + tx * 4)) = sg;
            float4 m = make_float4(xr.x * nmu * sg.x, xr.y * nmu * sg.y,
                                   xr.z * nmu * sg.z, xr.w * nmu * sg.w);
            *((float4*)(g_hcur + (size_t)gr * HH + tx * 4)) = m;
        }
    }
}

// ---------------- edge-mask: sigmoid(relu(A[src]+B[dst]+b1) . W2 + b2) ----------------
__global__ __launch_bounds__(256) void edge_mask_kernel(
    const int* __restrict__ src, const int* __restrict__ dst,
    const float* __restrict__ b1, const float* __restrict__ W2,
    const float* __restrict__ b2, float* __restrict__ out_em_k)
{
    __shared__ __align__(16) float b1s[64];
    __shared__ __align__(16) float w2s[64];
    int tid = threadIdx.x;
    if (tid < 64) { b1s[tid] = b1[tid]; w2s[tid] = W2[tid]; }
    __syncthreads();
    int idx = blockIdx.x * 256 + tid;
    int e = idx >> 4, lane = idx & 15;
    int s = src[e], d = dst[e];
    float4 a  = *((const float4*)(g_AB + (size_t)s * 128) + lane);
    float4 bb = *((const float4*)(g_AB + (size_t)d * 128 + 64) + lane);
    float4 bi = ((const float4*)b1s)[lane];
    float4 w  = ((const float4*)w2s)[lane];
    float p = fmaxf(a.x + bb.x + bi.x, 0.f) * w.x
            + fmaxf(a.y + bb.y + bi.y, 0.f) * w.y
            + fmaxf(a.z + bb.z + bi.z, 0.f) * w.z
            + fmaxf(a.w + bb.w + bi.w, 0.f) * w.w;
    #pragma unroll
    for (int off = 8; off > 0; off >>= 1)
        p += __shfl_down_sync(0xffffffffu, p, off, 16);
    if (lane == 0) {
        float sg = sigmoidf_(p + b2[0]);
        g_ew[e] = sg;
        out_em_k[(size_t)e * KK] = sg;
    }
}

// ---------------- pooling ----------------
__global__ __launch_bounds__(256) void pool_kernel(
    const float* __restrict__ h, const int* __restrict__ batch, float* __restrict__ pool)
{
    int idx = blockIdx.x * 256 + threadIdx.x;
    int n = idx >> 4, lane = idx & 15;
    int b = batch[n];
    float4 v = *((const float4*)(h + (size_t)n * HH) + lane);
    red_add_f4(((float4*)(pool + (size_t)b * HH)) + lane, v);
}

__global__ __launch_bounds__(256) void cnt_kernel(const int* __restrict__ batch)
{
    int idx = blockIdx.x * 256 + threadIdx.x;
    if (idx < NN) atomicAdd(&g_cnt[batch[idx]], 1);
}

// ---------------- finalize: means + classifier ----------------
__global__ __launch_bounds__(64) void finalize_kernel(
    const float* __restrict__ clfW, const float* __restrict__ clfb,
    float* __restrict__ out_logits, float* __restrict__ out_hstab,
    float* __restrict__ out_horig)
{
    int b = blockIdx.x, t = threadIdx.x;
    __shared__ float hs[64];
    float inv = 1.0f / fmaxf((float)g_cnt[b], 1.0f);
    out_horig[b * HH + t] = g_poolZ[b * HH + t] * inv;
    for (int k = 0; k < KK; k++) {
        float v = g_poolS[((size_t)k * NB_BATCH + b) * HH + t] * inv;
        out_hstab[((size_t)b * KK + k) * HH + t] = v;
        hs[t] = v;
        __syncthreads();
        if (t < CC) {
            float sacc = clfb[k * CC + t];
            #pragma unroll 8
            for (int h2 = 0; h2 < HH; h2++)
                sacc += hs[h2] * clfW[((size_t)k * HH + h2) * CC + t];
            out_logits[((size_t)b * KK + k) * CC + t] = sacc;
        }
        __syncthreads();
    }
}

// ---------------- host launch ----------------
extern "C" void kernel_launch(void* const* d_in, const int* in_sizes, int n_in,
                              void* d_out, int out_size)
{
    const float* x     = (const float*)d_in[0];
    const int*   ei    = (const int*)d_in[1];
    const int*   batch = (const int*)d_in[2];
    const float* ceW1  = (const float*)d_in[3];
    const float* ceb1  = (const float*)d_in[4];
    const float* ceW2  = (const float*)d_in[5];
    const float* ceb2  = (const float*)d_in[6];
    const float* ceeps = (const float*)d_in[7];
    const float* clW1  = (const float*)d_in[8];
    const float* clb1  = (const float*)d_in[9];
    const float* clW2  = (const float*)d_in[10];
    const float* clb2  = (const float*)d_in[11];
    const float* cleps = (const float*)d_in[12];
    const float* nmW1  = (const float*)d_in[13];
    const float* nmb1  = (const float*)d_in[14];
    const float* nmW2  = (const float*)d_in[15];
    const float* nmb2  = (const float*)d_in[16];
    const float* emW1  = (const float*)d_in[17];
    const float* emb1  = (const float*)d_in[18];
    const float* emW2  = (const float*)d_in[19];
    const float* emb2  = (const float*)d_in[20];
    const float* fmW1  = (const float*)d_in[21];
    const float* fmb1  = (const float*)d_in[22];
    const float* fmW2  = (const float*)d_in[23];
    const float* fmb2  = (const float*)d_in[24];
    const float* clfW  = (const float*)d_in[25];
    const float* clfb  = (const float*)d_in[26];

    const int* src = ei;
    const int* dst = ei + EE;

    float* Z_p;     cudaGetSymbolAddress((void**)&Z_p, g_Z);
    float* agg_p;   cudaGetSymbolAddress((void**)&agg_p, g_agg);
    float* hcur_p;  cudaGetSymbolAddress((void**)&hcur_p, g_hcur);
    float* ew_p;    cudaGetSymbolAddress((void**)&ew_p, g_ew);
    float* poolZ_p; cudaGetSymbolAddress((void**)&poolZ_p, g_poolZ);
    float* poolS_p; cudaGetSymbolAddress((void**)&poolS_p, g_poolS);
    int*   cnt_p;   cudaGetSymbolAddress((void**)&cnt_p, g_cnt);

    float* out        = (float*)d_out;
    float* out_logits = out;                                   // [B,K,C]
    float* out_hstab  = out_logits + NB_BATCH * KK * CC;       // [B,K,H]
    float* out_horig  = out_hstab + NB_BATCH * KK * HH;        // [B,H]
    float* out_nm     = out_horig + NB_BATCH * HH;             // [N,K,1]
    float* out_em     = out_nm + (size_t)NN * KK;              // [E,K,1]
    float* out_fm     = out_em + (size_t)EE * KK;              // [N,K,F]

    const int GB = (NN + 63) / 64;            // 782 row-tiles
    const int SCAT_GRID = (EE * 8) / 256;     // 25000
    const int EDGE_GRID = (EE * 16) / 256;    // 50000
    const int POOL_GRID = (NN * 16) / 256;    // 3125

    // ---- causal encoder GIN (3 layers) -> g_Z ----
    const float* hin = x;
    for (int l = 0; l < LL; l++) {
        cudaMemsetAsync(agg_p, 0, (size_t)NN * HH * sizeof(float));
        scatter_kernel<<<SCAT_GRID, 256>>>(hin, src, dst, nullptr);
        ginmlp_kernel<<<GB, 256>>>(hin, ceeps, l,
                                   ceW1 + (size_t)l * HH * HH, ceb1 + (size_t)l * HH,
                                   ceW2 + (size_t)l * HH * HH, ceb2 + (size_t)l * HH, Z_p);
        hin = Z_p;
    }

    // ---- node masks (all K) ----
    for (int k = 0; k < KK; k++)
        nm_kernel<<<GB, 256>>>(Z_p, nmW1 + (size_t)k * HH * HH, nmb1 + (size_t)k * HH,
                               nmW2 + (size_t)k * HH, nmb2 + k, out_nm + k);

    // ---- pooling setup + Z pool ----
    cudaMemsetAsync(cnt_p, 0, NB_BATCH * sizeof(int));
    cudaMemsetAsync(poolZ_p, 0, (size_t)NB_BATCH * HH * sizeof(float));
    cudaMemsetAsync(poolS_p, 0, (size_t)KK * NB_BATCH * HH * sizeof(float));
    cnt_kernel<<<(NN + 255) / 256, 256>>>(batch);
    pool_kernel<<<POOL_GRID, 256>>>(Z_p, batch, poolZ_p);

    // ---- per-expert pipeline ----
    for (int k = 0; k < KK; k++) {
        gemmAB_kernel<<<GB, 256>>>(Z_p, emW1 + (size_t)k * 2 * HH * HH);
        edge_mask_kernel<<<EDGE_GRID, 256>>>(src, dst, emb1 + (size_t)k * HH,
                                             emW2 + (size_t)k * HH, emb2 + k, out_em + k);
        fm_kernel<<<GB, 256>>>(Z_p, x, out_nm + k,
                               fmW1 + (size_t)k * HH * HH, fmb1 + (size_t)k * HH,
                               fmW2 + (size_t)k * HH * FF, fmb2 + (size_t)k * FF,
                               out_fm + (size_t)k * FF);
        for (int l = 0; l < LL; l++) {
            cudaMemsetAsync(agg_p, 0, (size_t)NN * HH * sizeof(float));
            scatter_kernel<<<SCAT_GRID, 256>>>(hcur_p, src, dst, ew_p);
            ginmlp_kernel<<<GB, 256>>>(hcur_p, cleps, l,
                                       clW1 + (size_t)l * HH * HH, clb1 + (size_t)l * HH,
                                       clW2 + (size_t)l * HH * HH, clb2 + (size_t)l * HH, hcur_p);
        }
        pool_kernel<<<POOL_GRID, 256>>>(hcur_p, batch, poolS_p + (size_t)k * NB_BATCH * HH);
    }

    // ---- finalize ----
    finalize_kernel<<<NB_BATCH, 64>>>(clfW, clfb, out_logits, out_hstab, out_horig);
}

// round 3
// speedup vs baseline: 1.3923x; 1.3923x over previous
#include <cuda_runtime.h>
#include <math.h>

#define NN 50000
#define EE 800000
#define HH 64
#define FF 64
#define CC 10
#define KK 4
#define LL 3
#define NB_BATCH 256
#define SPAD 68

// ---------------- device scratch ----------------
__device__ float g_Z[NN * HH];
__device__ float g_h0[(size_t)KK * NN * HH];
__device__ float g_h1[(size_t)KK * NN * HH];
__device__ float g_AB[(size_t)KK * NN * 128];
__device__ float g_ew[(size_t)KK * EE];
__device__ int   g_deg[NN];
__device__ int   g_off[NN + 1];
__device__ int   g_fill[NN];
__device__ int   g_csr_src[EE];
__device__ int   g_csr_eid[EE];
__device__ float g_poolZ[NB_BATCH * HH];
__device__ float g_poolS[KK * NB_BATCH * HH];
__device__ int   g_cnt[NB_BATCH];

__device__ __forceinline__ void red_add_f4(float4* p, float4 v) {
    asm volatile("red.global.add.v4.f32 [%0], {%1,%2,%3,%4};"
                 :: "l"(p), "f"(v.x), "f"(v.y), "f"(v.z), "f"(v.w) : "memory");
}
__device__ __forceinline__ float sigmoidf_(float v) { return 1.0f / (1.0f + expf(-v)); }

// load a 64x64 row-major weight matrix into Ws[k][col] layout
__device__ __forceinline__ void loadW(const float* __restrict__ W, float* Ws, int tid) {
    for (int i = tid; i < 1024; i += 256) {
        float4 w = ((const float4*)W)[i];
        *((float4*)&Ws[(i >> 4) * SPAD + (i & 15) * 4]) = w;
    }
}

// 64x64x64 GEMM microkernel: acc[i][j] = sum_k Ts[k][ty*4+i] * Ws[k][tx*4+j]
__device__ __forceinline__ void gemm64(const float* Ts, const float* Ws,
                                       float acc[4][4], int tx, int ty) {
    #pragma unroll
    for (int i = 0; i < 4; i++)
        #pragma unroll
        for (int j = 0; j < 4; j++) acc[i][j] = 0.f;
    #pragma unroll
    for (int k = 0; k < 64; k++) {
        float4 a4 = *((const float4*)&Ts[k * SPAD + ty * 4]);
        float4 b4 = *((const float4*)&Ws[k * SPAD + tx * 4]);
        float av[4] = {a4.x, a4.y, a4.z, a4.w}, bv[4] = {b4.x, b4.y, b4.z, b4.w};
        #pragma unroll
        for (int i = 0; i < 4; i++)
            #pragma unroll
            for (int j = 0; j < 4; j++) acc[i][j] = fmaf(av[i], bv[j], acc[i][j]);
    }
}

// ---------------- CSR build ----------------
__global__ __launch_bounds__(256) void hist_kernel(const int* __restrict__ dst) {
    int e = blockIdx.x * 256 + threadIdx.x;
    if (e < EE) atomicAdd(&g_deg[dst[e]], 1);
}

__global__ __launch_bounds__(1024) void scan_kernel() {
    __shared__ int wsum[32];
    __shared__ int carry_s;
    int tid = threadIdx.x, lane = tid & 31, wid = tid >> 5;
    if (tid == 0) carry_s = 0;
    __syncthreads();
    for (int base = 0; base < NN; base += 1024) {
        int v = (base + tid < NN) ? g_deg[base + tid] : 0;
        int inc = v;
        #pragma unroll
        for (int off = 1; off < 32; off <<= 1) {
            int t = __shfl_up_sync(0xffffffffu, inc, off);
            if (lane >= off) inc += t;
        }
        if (lane == 31) wsum[wid] = inc;
        __syncthreads();
        if (wid == 0) {
            int s = wsum[lane];
            #pragma unroll
            for (int off = 1; off < 32; off <<= 1) {
                int t = __shfl_up_sync(0xffffffffu, s, off);
                if (lane >= off) s += t;
            }
            wsum[lane] = s;
        }
        __syncthreads();
        int wpre = wid ? wsum[wid - 1] : 0;
        int excl = carry_s + wpre + inc - v;
        if (base + tid < NN) g_off[base + tid] = excl;
        __syncthreads();
        if (tid == 0) carry_s += wsum[31];
        __syncthreads();
    }
    if (threadIdx.x == 0) g_off[NN] = carry_s;
}

__global__ __launch_bounds__(256) void fill_kernel(const int* __restrict__ src,
                                                   const int* __restrict__ dst) {
    int e = blockIdx.x * 256 + threadIdx.x;
    if (e < EE) {
        int d = dst[e];
        int pos = g_off[d] + atomicAdd(&g_fill[d], 1);
        g_csr_src[pos] = src[e];
        g_csr_eid[pos] = e;
    }
}

// ---------------- fused GIN layer: CSR-aggregate + 2-layer MLP ----------------
// grid (tiles, K). h' = relu(relu(((1+eps)h + sum_j w*h_j)W1+b1)W2+b2)
__global__ __launch_bounds__(256) void ginfused_kernel(
    const float* __restrict__ hin, float* __restrict__ hout,
    const float* __restrict__ ew,          // null => unweighted (encoder)
    const float* __restrict__ eps_ptr, int lidx,
    const float* __restrict__ W1, const float* __restrict__ b1,
    const float* __restrict__ W2, const float* __restrict__ b2)
{
    __shared__ __align__(16) float Ts[64 * SPAD];
    __shared__ __align__(16) float Ws[64 * SPAD];
    __shared__ float bsh[64], bsh2[64];
    int tid = threadIdx.x;
    int k = blockIdx.y;
    const float* hin_k = hin + (size_t)k * NN * HH;
    float* hout_k = hout + (size_t)k * NN * HH;
    const float* ew_k = ew ? ew + (size_t)k * EE : nullptr;
    int r0 = blockIdx.x * 64;
    float epsv = 1.0f + eps_ptr[lidx];
    int row = tid >> 2, part = tid & 3;
    int gr = r0 + row;

    float a16[16];
    #pragma unroll
    for (int j = 0; j < 16; j++) a16[j] = 0.f;
    if (gr < NN) {
        const float4* hr = (const float4*)(hin_k + (size_t)gr * HH + part * 16);
        float4 h0 = hr[0], h1 = hr[1], h2 = hr[2], h3 = hr[3];
        a16[0]=epsv*h0.x;  a16[1]=epsv*h0.y;  a16[2]=epsv*h0.z;  a16[3]=epsv*h0.w;
        a16[4]=epsv*h1.x;  a16[5]=epsv*h1.y;  a16[6]=epsv*h1.z;  a16[7]=epsv*h1.w;
        a16[8]=epsv*h2.x;  a16[9]=epsv*h2.y;  a16[10]=epsv*h2.z; a16[11]=epsv*h2.w;
        a16[12]=epsv*h3.x; a16[13]=epsv*h3.y; a16[14]=epsv*h3.z; a16[15]=epsv*h3.w;
        int beg = g_off[gr], end = g_off[gr + 1];
        for (int p = beg; p < end; p++) {
            int s = g_csr_src[p];
            float w = 1.0f;
            if (ew_k) w = ew_k[g_csr_eid[p]];
            const float4* hs = (const float4*)(hin_k + (size_t)s * HH + part * 16);
            float4 v0 = hs[0], v1 = hs[1], v2 = hs[2], v3 = hs[3];
            a16[0]=fmaf(w,v0.x,a16[0]);  a16[1]=fmaf(w,v0.y,a16[1]);
            a16[2]=fmaf(w,v0.z,a16[2]);  a16[3]=fmaf(w,v0.w,a16[3]);
            a16[4]=fmaf(w,v1.x,a16[4]);  a16[5]=fmaf(w,v1.y,a16[5]);
            a16[6]=fmaf(w,v1.z,a16[6]);  a16[7]=fmaf(w,v1.w,a16[7]);
            a16[8]=fmaf(w,v2.x,a16[8]);  a16[9]=fmaf(w,v2.y,a16[9]);
            a16[10]=fmaf(w,v2.z,a16[10]); a16[11]=fmaf(w,v2.w,a16[11]);
            a16[12]=fmaf(w,v3.x,a16[12]); a16[13]=fmaf(w,v3.y,a16[13]);
            a16[14]=fmaf(w,v3.z,a16[14]); a16[15]=fmaf(w,v3.w,a16[15]);
        }
    }
    #pragma unroll
    for (int j = 0; j < 16; j++) Ts[(part * 16 + j) * SPAD + row] = a16[j];

    loadW(W1, Ws, tid);
    if (tid < 64) { bsh[tid] = b1[tid]; bsh2[tid] = b2[tid]; }
    __syncthreads();

    int tx = tid & 15, ty = tid >> 4;
    float acc[4][4];
    gemm64(Ts, Ws, acc, tx, ty);
    __syncthreads();
    #pragma unroll
    for (int i = 0; i < 4; i++)
        #pragma unroll
        for (int j = 0; j < 4; j++)
            Ts[(tx * 4 + j) * SPAD + ty * 4 + i] = fmaxf(acc[i][j] + bsh[tx * 4 + j], 0.f);
    loadW(W2, Ws, tid);
    __syncthreads();
    gemm64(Ts, Ws, acc, tx, ty);
    #pragma unroll
    for (int i = 0; i < 4; i++) {
        int go = r0 + ty * 4 + i;
        if (go < NN) {
            float4 o;
            o.x = fmaxf(acc[i][0] + bsh2[tx*4+0], 0.f);
            o.y = fmaxf(acc[i][1] + bsh2[tx*4+1], 0.f);
            o.z = fmaxf(acc[i][2] + bsh2[tx*4+2], 0.f);
            o.w = fmaxf(acc[i][3] + bsh2[tx*4+3], 0.f);
            *((float4*)(hout_k + (size_t)go * HH + tx * 4)) = o;
        }
    }
}

// ---------------- fused mask kernel: nm + AB precompute + fm + masked_x ----------------
// grid (tiles, K)
__global__ __launch_bounds__(256) void mask_kernel(
    const float* __restrict__ Z, const float* __restrict__ x,
    const float* __restrict__ nmW1, const float* __restrict__ nmb1,
    const float* __restrict__ nmW2, const float* __restrict__ nmb2,
    const float* __restrict__ emW1,
    const float* __restrict__ fmW1, const float* __restrict__ fmb1,
    const float* __restrict__ fmW2, const float* __restrict__ fmb2,
    float* __restrict__ out_nm, float* __restrict__ out_fm)
{
    __shared__ __align__(16) float Ts[64 * SPAD];
    __shared__ __align__(16) float Ws[64 * SPAD];
    __shared__ float bsh[64], bsh2[64], w2s[64], nmv[64];
    int tid = threadIdx.x, r0 = blockIdx.x * 64;
    int k = blockIdx.y;
    const float* nmW1k = nmW1 + (size_t)k * 4096;
    const float* nmb1k = nmb1 + (size_t)k * 64;
    const float* nmW2k = nmW2 + (size_t)k * 64;
    const float* emW1k = emW1 + (size_t)k * 8192;
    const float* fmW1k = fmW1 + (size_t)k * 4096;
    const float* fmb1k = fmb1 + (size_t)k * 64;
    const float* fmW2k = fmW2 + (size_t)k * 4096;
    const float* fmb2k = fmb2 + (size_t)k * 64;
    float* ABk = g_AB + (size_t)k * NN * 128;
    float* hcur_k = g_h0 + (size_t)k * NN * HH;

    {   // load Z tile transposed
        int row = tid >> 2, part = tid & 3, gr = r0 + row;
        #pragma unroll
        for (int q = 0; q < 4; q++) {
            float4 v = make_float4(0.f, 0.f, 0.f, 0.f);
            if (gr < NN) v = *((const float4*)(Z + (size_t)gr * HH + part * 16 + q * 4));
            int c = part * 16 + q * 4;
            Ts[(c+0)*SPAD + row] = v.x; Ts[(c+1)*SPAD + row] = v.y;
            Ts[(c+2)*SPAD + row] = v.z; Ts[(c+3)*SPAD + row] = v.w;
        }
    }
    int tx = tid & 15, ty = tid >> 4;
    float acc[4][4];

    // ---- node mask ----
    loadW(nmW1k, Ws, tid);
    if (tid < 64) { bsh[tid] = nmb1k[tid]; w2s[tid] = nmW2k[tid]; }
    __syncthreads();
    gemm64(Ts, Ws, acc, tx, ty);
    float b2v = nmb2[k];
    #pragma unroll
    for (int i = 0; i < 4; i++) {
        float p = 0.f;
        #pragma unroll
        for (int j = 0; j < 4; j++)
            p += fmaxf(acc[i][j] + bsh[tx*4+j], 0.f) * w2s[tx*4+j];
        #pragma unroll
        for (int off = 8; off > 0; off >>= 1)
            p += __shfl_down_sync(0xffffffffu, p, off, 16);
        if (tx == 0) {
            float sg = sigmoidf_(p + b2v);
            nmv[ty * 4 + i] = sg;
            int gr = r0 + ty * 4 + i;
            if (gr < NN) out_nm[(size_t)gr * KK + k] = sg;
        }
    }

    // ---- AB precompute (2 halves of em_W1) ----
    #pragma unroll
    for (int half = 0; half < 2; half++) {
        __syncthreads();
        loadW(emW1k + half * 4096, Ws, tid);
        __syncthreads();
        gemm64(Ts, Ws, acc, tx, ty);
        #pragma unroll
        for (int i = 0; i < 4; i++) {
            int gr = r0 + ty * 4 + i;
            if (gr < NN) {
                float4 o = make_float4(acc[i][0], acc[i][1], acc[i][2], acc[i][3]);
                *((float4*)(ABk + (size_t)gr * 128 + half * 64 + tx * 4)) = o;
            }
        }
    }

    // ---- feature mask + masked_x ----
    __syncthreads();
    loadW(fmW1k, Ws, tid);
    if (tid < 64) { bsh[tid] = fmb1k[tid]; bsh2[tid] = fmb2k[tid]; }
    __syncthreads();
    gemm64(Ts, Ws, acc, tx, ty);
    __syncthreads();
    #pragma unroll
    for (int i = 0; i < 4; i++)
        #pragma unroll
        for (int j = 0; j < 4; j++)
            Ts[(tx * 4 + j) * SPAD + ty * 4 + i] = fmaxf(acc[i][j] + bsh[tx*4+j], 0.f);
    loadW(fmW2k, Ws, tid);
    __syncthreads();
    gemm64(Ts, Ws, acc, tx, ty);
    #pragma unroll
    for (int i = 0; i < 4; i++) {
        int gr = r0 + ty * 4 + i;
        if (gr < NN) {
            float nmu = nmv[ty * 4 + i];
            float4 xr = *((const float4*)(x + (size_t)gr * FF + tx * 4));
            float4 sg;
            sg.x = sigmoidf_(acc[i][0] + bsh2[tx*4+0]);
            sg.y = sigmoidf_(acc[i][1] + bsh2[tx*4+1]);
            sg.z = sigmoidf_(acc[i][2] + bsh2[tx*4+2]);
            sg.w = sigmoidf_(acc[i][3] + bsh2[tx*4+3]);
            *((float4*)(out_fm + ((size_t)gr * KK + k) * FF + tx * 4)) = sg;
            float4 m = make_float4(xr.x * nmu * sg.x, xr.y * nmu * sg.y,
                                   xr.z * nmu * sg.z, xr.w * nmu * sg.w);
            *((float4*)(hcur_k + (size_t)gr * HH + tx * 4)) = m;
        }
    }
}

// ---------------- edge mask: sigmoid(relu(A[src]+B[dst]+b1) . W2 + b2) ----------------
// grid (E*16/256, K)
__global__ __launch_bounds__(256) void edge_mask_kernel(
    const int* __restrict__ src, const int* __restrict__ dst,
    const float* __restrict__ emb1, const float* __restrict__ emW2,
    const float* __restrict__ emb2, float* __restrict__ out_em)
{
    __shared__ __align__(16) float b1s[64];
    __shared__ __align__(16) float w2s[64];
    int tid = threadIdx.x;
    int k = blockIdx.y;
    if (tid < 64) { b1s[tid] = emb1[k * 64 + tid]; w2s[tid] = emW2[k * 64 + tid]; }
    __syncthreads();
    const float* ABk = g_AB + (size_t)k * NN * 128;
    float* ewk = g_ew + (size_t)k * EE;
    int idx = blockIdx.x * 256 + tid;
    int e = idx >> 4, lane = idx & 15;
    int s = src[e], d = dst[e];
    float4 a  = *((const float4*)(ABk + (size_t)s * 128) + lane);
    float4 bb = *((const float4*)(ABk + (size_t)d * 128 + 64) + lane);
    float4 bi = ((const float4*)b1s)[lane];
    float4 w  = ((const float4*)w2s)[lane];
    float p = fmaxf(a.x + bb.x + bi.x, 0.f) * w.x
            + fmaxf(a.y + bb.y + bi.y, 0.f) * w.y
            + fmaxf(a.z + bb.z + bi.z, 0.f) * w.z
            + fmaxf(a.w + bb.w + bi.w, 0.f) * w.w;
    #pragma unroll
    for (int off = 8; off > 0; off >>= 1)
        p += __shfl_down_sync(0xffffffffu, p, off, 16);
    if (lane == 0) {
        float sg = sigmoidf_(p + emb2[k]);
        ewk[e] = sg;
        out_em[(size_t)e * KK + k] = sg;
    }
}

// ---------------- pooling ----------------
__global__ __launch_bounds__(256) void poolZ_kernel(const int* __restrict__ batch) {
    int idx = blockIdx.x * 256 + threadIdx.x;
    int n = idx >> 4, lane = idx & 15;
    int b = batch[n];
    float4 v = *((const float4*)(g_Z + (size_t)n * HH) + lane);
    red_add_f4(((float4*)(g_poolZ + (size_t)b * HH)) + lane, v);
}
__global__ __launch_bounds__(256) void poolS_kernel(const int* __restrict__ batch) {
    int idx = blockIdx.x * 256 + threadIdx.x;
    int k = blockIdx.y;
    int n = idx >> 4, lane = idx & 15;
    int b = batch[n];
    float4 v = *((const float4*)(g_h1 + (size_t)k * NN * HH + (size_t)n * HH) + lane);
    red_add_f4(((float4*)(g_poolS + ((size_t)k * NB_BATCH + b) * HH)) + lane, v);
}
__global__ __launch_bounds__(256) void cnt_kernel(const int* __restrict__ batch) {
    int idx = blockIdx.x * 256 + threadIdx.x;
    if (idx < NN) atomicAdd(&g_cnt[batch[idx]], 1);
}

// ---------------- finalize ----------------
__global__ __launch_bounds__(64) void finalize_kernel(
    const float* __restrict__ clfW, const float* __restrict__ clfb,
    float* __restrict__ out_logits, float* __restrict__ out_hstab,
    float* __restrict__ out_horig)
{
    int b = blockIdx.x, t = threadIdx.x;
    __shared__ float hs[64];
    float inv = 1.0f / fmaxf((float)g_cnt[b], 1.0f);
    out_horig[b * HH + t] = g_poolZ[b * HH + t] * inv;
    for (int k = 0; k < KK; k++) {
        float v = g_poolS[((size_t)k * NB_BATCH + b) * HH + t] * inv;
        out_hstab[((size_t)b * KK + k) * HH + t] = v;
        hs[t] = v;
        __syncthreads();
        if (t < CC) {
            float sacc = clfb[k * CC + t];
            #pragma unroll 8
            for (int h2 = 0; h2 < HH; h2++)
                sacc += hs[h2] * clfW[((size_t)k * HH + h2) * CC + t];
            out_logits[((size_t)b * KK + k) * CC + t] = sacc;
        }
        __syncthreads();
    }
}

// ---------------- host launch ----------------
extern "C" void kernel_launch(void* const* d_in, const int* in_sizes, int n_in,
                              void* d_out, int out_size)
{
    const float* x     = (const float*)d_in[0];
    const int*   ei    = (const int*)d_in[1];
    const int*   batch = (const int*)d_in[2];
    const float* ceW1  = (const float*)d_in[3];
    const float* ceb1  = (const float*)d_in[4];
    const float* ceW2  = (const float*)d_in[5];
    const float* ceb2  = (const float*)d_in[6];
    const float* ceeps = (const float*)d_in[7];
    const float* clW1  = (const float*)d_in[8];
    const float* clb1  = (const float*)d_in[9];
    const float* clW2  = (const float*)d_in[10];
    const float* clb2  = (const float*)d_in[11];
    const float* cleps = (const float*)d_in[12];
    const float* nmW1  = (const float*)d_in[13];
    const float* nmb1  = (const float*)d_in[14];
    const float* nmW2  = (const float*)d_in[15];
    const float* nmb2  = (const float*)d_in[16];
    const float* emW1  = (const float*)d_in[17];
    const float* emb1  = (const float*)d_in[18];
    const float* emW2  = (const float*)d_in[19];
    const float* emb2  = (const float*)d_in[20];
    const float* fmW1  = (const float*)d_in[21];
    const float* fmb1  = (const float*)d_in[22];
    const float* fmW2  = (const float*)d_in[23];
    const float* fmb2  = (const float*)d_in[24];
    const float* clfW  = (const float*)d_in[25];
    const float* clfb  = (const float*)d_in[26];

    const int* src = ei;
    const int* dst = ei + EE;

    float* Z_p;     cudaGetSymbolAddress((void**)&Z_p, g_Z);
    float* h0_p;    cudaGetSymbolAddress((void**)&h0_p, g_h0);
    float* h1_p;    cudaGetSymbolAddress((void**)&h1_p, g_h1);
    float* ew_p;    cudaGetSymbolAddress((void**)&ew_p, g_ew);
    float* poolZ_p; cudaGetSymbolAddress((void**)&poolZ_p, g_poolZ);
    float* poolS_p; cudaGetSymbolAddress((void**)&poolS_p, g_poolS);
    int*   cnt_p;   cudaGetSymbolAddress((void**)&cnt_p, g_cnt);
    int*   deg_p;   cudaGetSymbolAddress((void**)&deg_p, g_deg);
    int*   fill_p;  cudaGetSymbolAddress((void**)&fill_p, g_fill);

    float* out        = (float*)d_out;
    float* out_logits = out;
    float* out_hstab  = out_logits + NB_BATCH * KK * CC;
    float* out_horig  = out_hstab + NB_BATCH * KK * HH;
    float* out_nm     = out_horig + NB_BATCH * HH;
    float* out_em     = out_nm + (size_t)NN * KK;
    float* out_fm     = out_em + (size_t)EE * KK;

    const int GB = (NN + 63) / 64;          // 782
    const int EG = (EE + 255) / 256;        // 3125
    const int EDGE_GRID = (EE * 16) / 256;  // 50000
    const int POOL_GRID = (NN * 16) / 256;  // 3125

    // ---- CSR build ----
    cudaMemsetAsync(deg_p, 0, NN * sizeof(int));
    cudaMemsetAsync(fill_p, 0, NN * sizeof(int));
    hist_kernel<<<EG, 256>>>(dst);
    scan_kernel<<<1, 1024>>>();
    fill_kernel<<<EG, 256>>>(src, dst);

    // ---- causal encoder GIN (3 layers), k=0 buffers ----
    ginfused_kernel<<<dim3(GB, 1), 256>>>(x, h0_p, nullptr, ceeps, 0,
                                          ceW1, ceb1, ceW2, ceb2);
    ginfused_kernel<<<dim3(GB, 1), 256>>>(h0_p, h1_p, nullptr, ceeps, 1,
                                          ceW1 + 4096, ceb1 + 64, ceW2 + 4096, ceb2 + 64);
    ginfused_kernel<<<dim3(GB, 1), 256>>>(h1_p, Z_p, nullptr, ceeps, 2,
                                          ceW1 + 8192, ceb1 + 128, ceW2 + 8192, ceb2 + 128);

    // ---- masks (all K): nm + AB + fm + masked_x -> g_h0 ----
    mask_kernel<<<dim3(GB, KK), 256>>>(Z_p, x, nmW1, nmb1, nmW2, nmb2,
                                       emW1, fmW1, fmb1, fmW2, fmb2,
                                       out_nm, out_fm);
    edge_mask_kernel<<<dim3(EDGE_GRID, KK), 256>>>(src, dst, emb1, emW2, emb2, out_em);

    // ---- classifier GIN (3 layers, all K in parallel) ----
    ginfused_kernel<<<dim3(GB, KK), 256>>>(h0_p, h1_p, ew_p, cleps, 0,
                                           clW1, clb1, clW2, clb2);
    ginfused_kernel<<<dim3(GB, KK), 256>>>(h1_p, h0_p, ew_p, cleps, 1,
                                           clW1 + 4096, clb1 + 64, clW2 + 4096, clb2 + 64);
    ginfused_kernel<<<dim3(GB, KK), 256>>>(h0_p, h1_p, ew_p, cleps, 2,
                                           clW1 + 8192, clb1 + 128, clW2 + 8192, clb2 + 128);

    // ---- pooling + finalize ----
    cudaMemsetAsync(cnt_p, 0, NB_BATCH * sizeof(int));
    cudaMemsetAsync(poolZ_p, 0, (size_t)NB_BATCH * HH * sizeof(float));
    cudaMemsetAsync(poolS_p, 0, (size_t)KK * NB_BATCH * HH * sizeof(float));
    cnt_kernel<<<(NN + 255) / 256, 256>>>(batch);
    poolZ_kernel<<<POOL_GRID, 256>>>(batch);
    poolS_kernel<<<dim3(POOL_GRID, KK), 256>>>(batch);
    finalize_kernel<<<NB_BATCH, 64>>>(clfW, clfb, out_logits, out_hstab, out_horig);
}

// round 4
// speedup vs baseline: 1.6037x; 1.1518x over previous
#include <cuda_runtime.h>
#include <math.h>

#define NN 50000
#define EE 800000
#define HH 64
#define FF 64
#define CC 10
#define KK 4
#define LL 3
#define NB_BATCH 256
#define SPAD 68

// ---------------- device scratch ----------------
__device__ float g_Z[NN * HH];
__device__ float g_h0[(size_t)KK * NN * HH];
__device__ float g_h1[(size_t)KK * NN * HH];
__device__ float g_AB[(size_t)KK * NN * 128];
__device__ float g_ew[(size_t)KK * EE];
__device__ int   g_deg[NN];
__device__ int   g_off[NN + 1];
__device__ int   g_fill[NN];
__device__ int   g_csr_src[EE];
__device__ int   g_csr_eid[EE];
__device__ float g_poolZ[NB_BATCH * HH];
__device__ float g_poolS[KK * NB_BATCH * HH];
__device__ int   g_cnt[NB_BATCH];

__device__ __forceinline__ void red_add_f4(float4* p, float4 v) {
    asm volatile("red.global.add.v4.f32 [%0], {%1,%2,%3,%4};"
                 :: "l"(p), "f"(v.x), "f"(v.y), "f"(v.z), "f"(v.w) : "memory");
}
__device__ __forceinline__ float sigmoidf_(float v) { return 1.0f / (1.0f + expf(-v)); }

// load 64x64 row-major weight matrix into Ws[k][col] (SPAD stride) - conflict-free
__device__ __forceinline__ void loadW(const float* __restrict__ W, float* Ws, int tid) {
    for (int i = tid; i < 1024; i += 256) {
        float4 w = ((const float4*)W)[i];
        *((float4*)&Ws[(i >> 4) * SPAD + (i & 15) * 4]) = w;
    }
}

// 64x64x64 GEMM: As row-major [row][k], Ws [k][col]; acc[i][j] = row ty*4+i, col tx*4+j
__device__ __forceinline__ void gemm64(const float* As, const float* Ws,
                                       float acc[4][4], int tx, int ty) {
    #pragma unroll
    for (int i = 0; i < 4; i++)
        #pragma unroll
        for (int j = 0; j < 4; j++) acc[i][j] = 0.f;
    #pragma unroll
    for (int kk = 0; kk < 64; kk += 4) {
        float bv[4][4];
        #pragma unroll
        for (int s = 0; s < 4; s++) {
            float4 b4 = *((const float4*)&Ws[(kk + s) * SPAD + tx * 4]);
            bv[s][0] = b4.x; bv[s][1] = b4.y; bv[s][2] = b4.z; bv[s][3] = b4.w;
        }
        #pragma unroll
        for (int i = 0; i < 4; i++) {
            float4 a4 = *((const float4*)&As[(ty * 4 + i) * SPAD + kk]);
            float av[4] = {a4.x, a4.y, a4.z, a4.w};
            #pragma unroll
            for (int s = 0; s < 4; s++)
                #pragma unroll
                for (int j = 0; j < 4; j++)
                    acc[i][j] = fmaf(av[s], bv[s][j], acc[i][j]);
        }
    }
}

// ---------------- CSR build ----------------
__global__ __launch_bounds__(256) void hist_kernel(const int* __restrict__ dst) {
    int e = blockIdx.x * 256 + threadIdx.x;
    if (e < EE) atomicAdd(&g_deg[dst[e]], 1);
}

__global__ __launch_bounds__(1024) void scan_kernel() {
    __shared__ int wsum[32];
    __shared__ int carry_s;
    int tid = threadIdx.x, lane = tid & 31, wid = tid >> 5;
    if (tid == 0) carry_s = 0;
    __syncthreads();
    for (int base = 0; base < NN; base += 1024) {
        int v = (base + tid < NN) ? g_deg[base + tid] : 0;
        int inc = v;
        #pragma unroll
        for (int off = 1; off < 32; off <<= 1) {
            int t = __shfl_up_sync(0xffffffffu, inc, off);
            if (lane >= off) inc += t;
        }
        if (lane == 31) wsum[wid] = inc;
        __syncthreads();
        if (wid == 0) {
            int s = wsum[lane];
            #pragma unroll
            for (int off = 1; off < 32; off <<= 1) {
                int t = __shfl_up_sync(0xffffffffu, s, off);
                if (lane >= off) s += t;
            }
            wsum[lane] = s;
        }
        __syncthreads();
        int wpre = wid ? wsum[wid - 1] : 0;
        int excl = carry_s + wpre + inc - v;
        if (base + tid < NN) g_off[base + tid] = excl;
        __syncthreads();
        if (tid == 0) carry_s += wsum[31];
        __syncthreads();
    }
    if (threadIdx.x == 0) g_off[NN] = carry_s;
}

__global__ __launch_bounds__(256) void fill_kernel(const int* __restrict__ src,
                                                   const int* __restrict__ dst) {
    int e = blockIdx.x * 256 + threadIdx.x;
    if (e < EE) {
        int d = dst[e];
        int pos = g_off[d] + atomicAdd(&g_fill[d], 1);
        g_csr_src[pos] = src[e];
        g_csr_eid[pos] = e;
    }
}

// ---------------- fused GIN layer: CSR-aggregate + 2-layer MLP ----------------
// grid (tiles, K). 16 threads/row gather, 4 rows sequential per 16-lane group.
__global__ __launch_bounds__(256) void ginfused_kernel(
    const float* __restrict__ hin, float* __restrict__ hout,
    const float* __restrict__ ew,          // null => unweighted (encoder)
    const float* __restrict__ eps_ptr, int lidx,
    const float* __restrict__ W1, const float* __restrict__ b1,
    const float* __restrict__ W2, const float* __restrict__ b2)
{
    __shared__ __align__(16) float As[64 * SPAD];
    __shared__ __align__(16) float Ws[64 * SPAD];
    __shared__ float bsh[64], bsh2[64];
    int tid = threadIdx.x;
    int k = blockIdx.y;
    const float* hin_k = hin + (size_t)k * NN * HH;
    float* hout_k = hout + (size_t)k * NN * HH;
    const float* ew_k = ew ? ew + (size_t)k * EE : nullptr;
    int r0 = blockIdx.x * 64;
    float epsv = 1.0f + eps_ptr[lidx];

    int part = tid & 15;     // float4 index within 64-float row
    int grp = tid >> 4;      // 0..15

    #pragma unroll
    for (int rr = 0; rr < 4; rr++) {
        int row = rr * 16 + grp;
        int gr = r0 + row;
        float4 a = make_float4(0.f, 0.f, 0.f, 0.f);
        if (gr < NN) {
            const float4* hr = (const float4*)(hin_k + (size_t)gr * HH);
            float4 h = hr[part];
            a.x = epsv * h.x; a.y = epsv * h.y; a.z = epsv * h.z; a.w = epsv * h.w;
            int beg = g_off[gr], end = g_off[gr + 1];
            int p = beg;
            if (ew_k) {
                for (; p + 1 < end; p += 2) {
                    int s0 = g_csr_src[p], s1 = g_csr_src[p + 1];
                    float w0 = ew_k[g_csr_eid[p]], w1 = ew_k[g_csr_eid[p + 1]];
                    float4 v0 = ((const float4*)(hin_k + (size_t)s0 * HH))[part];
                    float4 v1 = ((const float4*)(hin_k + (size_t)s1 * HH))[part];
                    a.x = fmaf(w0, v0.x, a.x); a.y = fmaf(w0, v0.y, a.y);
                    a.z = fmaf(w0, v0.z, a.z); a.w = fmaf(w0, v0.w, a.w);
                    a.x = fmaf(w1, v1.x, a.x); a.y = fmaf(w1, v1.y, a.y);
                    a.z = fmaf(w1, v1.z, a.z); a.w = fmaf(w1, v1.w, a.w);
                }
                if (p < end) {
                    int s0 = g_csr_src[p];
                    float w0 = ew_k[g_csr_eid[p]];
                    float4 v0 = ((const float4*)(hin_k + (size_t)s0 * HH))[part];
                    a.x = fmaf(w0, v0.x, a.x); a.y = fmaf(w0, v0.y, a.y);
                    a.z = fmaf(w0, v0.z, a.z); a.w = fmaf(w0, v0.w, a.w);
                }
            } else {
                for (; p + 1 < end; p += 2) {
                    int s0 = g_csr_src[p], s1 = g_csr_src[p + 1];
                    float4 v0 = ((const float4*)(hin_k + (size_t)s0 * HH))[part];
                    float4 v1 = ((const float4*)(hin_k + (size_t)s1 * HH))[part];
                    a.x += v0.x + v1.x; a.y += v0.y + v1.y;
                    a.z += v0.z + v1.z; a.w += v0.w + v1.w;
                }
                if (p < end) {
                    int s0 = g_csr_src[p];
                    float4 v0 = ((const float4*)(hin_k + (size_t)s0 * HH))[part];
                    a.x += v0.x; a.y += v0.y; a.z += v0.z; a.w += v0.w;
                }
            }
        }
        *((float4*)&As[row * SPAD + part * 4]) = a;   // conflict-free STS.128
    }

    loadW(W1, Ws, tid);
    if (tid < 64) { bsh[tid] = b1[tid]; bsh2[tid] = b2[tid]; }
    __syncthreads();

    int tx = tid & 15, ty = tid >> 4;
    float acc[4][4];
    gemm64(As, Ws, acc, tx, ty);
    __syncthreads();
    #pragma unroll
    for (int i = 0; i < 4; i++) {
        float4 h;
        h.x = fmaxf(acc[i][0] + bsh[tx*4+0], 0.f);
        h.y = fmaxf(acc[i][1] + bsh[tx*4+1], 0.f);
        h.z = fmaxf(acc[i][2] + bsh[tx*4+2], 0.f);
        h.w = fmaxf(acc[i][3] + bsh[tx*4+3], 0.f);
        *((float4*)&As[(ty * 4 + i) * SPAD + tx * 4]) = h;
    }
    loadW(W2, Ws, tid);
    __syncthreads();
    gemm64(As, Ws, acc, tx, ty);
    #pragma unroll
    for (int i = 0; i < 4; i++) {
        int go = r0 + ty * 4 + i;
        if (go < NN) {
            float4 o;
            o.x = fmaxf(acc[i][0] + bsh2[tx*4+0], 0.f);
            o.y = fmaxf(acc[i][1] + bsh2[tx*4+1], 0.f);
            o.z = fmaxf(acc[i][2] + bsh2[tx*4+2], 0.f);
            o.w = fmaxf(acc[i][3] + bsh2[tx*4+3], 0.f);
            *((float4*)(hout_k + (size_t)go * HH + tx * 4)) = o;
        }
    }
}

// ---------------- fused mask kernel: nm + AB precompute + fm + masked_x ----------------
__global__ __launch_bounds__(256) void mask_kernel(
    const float* __restrict__ Z, const float* __restrict__ x,
    const float* __restrict__ nmW1, const float* __restrict__ nmb1,
    const float* __restrict__ nmW2, const float* __restrict__ nmb2,
    const float* __restrict__ emW1,
    const float* __restrict__ fmW1, const float* __restrict__ fmb1,
    const float* __restrict__ fmW2, const float* __restrict__ fmb2,
    float* __restrict__ out_nm, float* __restrict__ out_fm)
{
    __shared__ __align__(16) float As[64 * SPAD];
    __shared__ __align__(16) float Ws[64 * SPAD];
    __shared__ float bsh[64], bsh2[64], w2s[64], nmv[64];
    int tid = threadIdx.x, r0 = blockIdx.x * 64;
    int k = blockIdx.y;
    const float* nmW1k = nmW1 + (size_t)k * 4096;
    const float* nmb1k = nmb1 + (size_t)k * 64;
    const float* nmW2k = nmW2 + (size_t)k * 64;
    const float* emW1k = emW1 + (size_t)k * 8192;
    const float* fmW1k = fmW1 + (size_t)k * 4096;
    const float* fmb1k = fmb1 + (size_t)k * 64;
    const float* fmW2k = fmW2 + (size_t)k * 4096;
    const float* fmb2k = fmb2 + (size_t)k * 64;
    float* ABk = g_AB + (size_t)k * NN * 128;
    float* hcur_k = g_h0 + (size_t)k * NN * HH;

    {   // load Z tile row-major, conflict-free
        int row = tid >> 2, p0 = (tid & 3) * 4, gr = r0 + row;
        #pragma unroll
        for (int q = 0; q < 4; q++) {
            float4 v = make_float4(0.f, 0.f, 0.f, 0.f);
            if (gr < NN) v = ((const float4*)(Z + (size_t)gr * HH))[p0 + q];
            *((float4*)&As[row * SPAD + (p0 + q) * 4]) = v;
        }
    }
    int tx = tid & 15, ty = tid >> 4;
    float acc[4][4];

    // ---- node mask ----
    loadW(nmW1k, Ws, tid);
    if (tid < 64) { bsh[tid] = nmb1k[tid]; w2s[tid] = nmW2k[tid]; }
    __syncthreads();
    gemm64(As, Ws, acc, tx, ty);
    float b2v = nmb2[k];
    #pragma unroll
    for (int i = 0; i < 4; i++) {
        float p = 0.f;
        #pragma unroll
        for (int j = 0; j < 4; j++)
            p += fmaxf(acc[i][j] + bsh[tx*4+j], 0.f) * w2s[tx*4+j];
        #pragma unroll
        for (int off = 8; off > 0; off >>= 1)
            p += __shfl_down_sync(0xffffffffu, p, off, 16);
        if (tx == 0) {
            float sg = sigmoidf_(p + b2v);
            nmv[ty * 4 + i] = sg;
            int gr = r0 + ty * 4 + i;
            if (gr < NN) out_nm[(size_t)gr * KK + k] = sg;
        }
    }

    // ---- AB precompute ----
    #pragma unroll
    for (int half = 0; half < 2; half++) {
        __syncthreads();
        loadW(emW1k + half * 4096, Ws, tid);
        __syncthreads();
        gemm64(As, Ws, acc, tx, ty);
        #pragma unroll
        for (int i = 0; i < 4; i++) {
            int gr = r0 + ty * 4 + i;
            if (gr < NN) {
                float4 o = make_float4(acc[i][0], acc[i][1], acc[i][2], acc[i][3]);
                *((float4*)(ABk + (size_t)gr * 128 + half * 64 + tx * 4)) = o;
            }
        }
    }

    // ---- feature mask + masked_x ----
    __syncthreads();
    loadW(fmW1k, Ws, tid);
    if (tid < 64) { bsh[tid] = fmb1k[tid]; bsh2[tid] = fmb2k[tid]; }
    __syncthreads();
    gemm64(As, Ws, acc, tx, ty);
    __syncthreads();
    #pragma unroll
    for (int i = 0; i < 4; i++) {
        float4 h;
        h.x = fmaxf(acc[i][0] + bsh[tx*4+0], 0.f);
        h.y = fmaxf(acc[i][1] + bsh[tx*4+1], 0.f);
        h.z = fmaxf(acc[i][2] + bsh[tx*4+2], 0.f);
        h.w = fmaxf(acc[i][3] + bsh[tx*4+3], 0.f);
        *((float4*)&As[(ty * 4 + i) * SPAD + tx * 4]) = h;
    }
    loadW(fmW2k, Ws, tid);
    __syncthreads();
    gemm64(As, Ws, acc, tx, ty);
    #pragma unroll
    for (int i = 0; i < 4; i++) {
        int gr = r0 + ty * 4 + i;
        if (gr < NN) {
            float nmu = nmv[ty * 4 + i];
            float4 xr = *((const float4*)(x + (size_t)gr * FF + tx * 4));
            float4 sg;
            sg.x = sigmoidf_(acc[i][0] + bsh2[tx*4+0]);
            sg.y = sigmoidf_(acc[i][1] + bsh2[tx*4+1]);
            sg.z = sigmoidf_(acc[i][2] + bsh2[tx*4+2]);
            sg.w = sigmoidf_(acc[i][3] + bsh2[tx*4+3]);
            *((float4*)(out_fm + ((size_t)gr * KK + k) * FF + tx * 4)) = sg;
            float4 m = make_float4(xr.x * nmu * sg.x, xr.y * nmu * sg.y,
                                   xr.z * nmu * sg.z, xr.w * nmu * sg.w);
            *((float4*)(hcur_k + (size_t)gr * HH + tx * 4)) = m;
        }
    }
}

// ---------------- edge mask ----------------
__global__ __launch_bounds__(256) void edge_mask_kernel(
    const int* __restrict__ src, const int* __restrict__ dst,
    const float* __restrict__ emb1, const float* __restrict__ emW2,
    const float* __restrict__ emb2, float* __restrict__ out_em)
{
    __shared__ __align__(16) float b1s[64];
    __shared__ __align__(16) float w2s[64];
    int tid = threadIdx.x;
    int k = blockIdx.y;
    if (tid < 64) { b1s[tid] = emb1[k * 64 + tid]; w2s[tid] = emW2[k * 64 + tid]; }
    __syncthreads();
    const float* ABk = g_AB + (size_t)k * NN * 128;
    float* ewk = g_ew + (size_t)k * EE;
    int idx = blockIdx.x * 256 + tid;
    int e = idx >> 4, lane = idx & 15;
    int s = src[e], d = dst[e];
    float4 a  = *((const float4*)(ABk + (size_t)s * 128) + lane);
    float4 bb = *((const float4*)(ABk + (size_t)d * 128 + 64) + lane);
    float4 bi = ((const float4*)b1s)[lane];
    float4 w  = ((const float4*)w2s)[lane];
    float p = fmaxf(a.x + bb.x + bi.x, 0.f) * w.x
            + fmaxf(a.y + bb.y + bi.y, 0.f) * w.y
            + fmaxf(a.z + bb.z + bi.z, 0.f) * w.z
            + fmaxf(a.w + bb.w + bi.w, 0.f) * w.w;
    #pragma unroll
    for (int off = 8; off > 0; off >>= 1)
        p += __shfl_down_sync(0xffffffffu, p, off, 16);
    if (lane == 0) {
        float sg = sigmoidf_(p + emb2[k]);
        ewk[e] = sg;
        out_em[(size_t)e * KK + k] = sg;
    }
}

// ---------------- pooling ----------------
__global__ __launch_bounds__(256) void poolZ_kernel(const int* __restrict__ batch) {
    int idx = blockIdx.x * 256 + threadIdx.x;
    int n = idx >> 4, lane = idx & 15;
    int b = batch[n];
    float4 v = *((const float4*)(g_Z + (size_t)n * HH) + lane);
    red_add_f4(((float4*)(g_poolZ + (size_t)b * HH)) + lane, v);
}
__global__ __launch_bounds__(256) void poolS_kernel(const int* __restrict__ batch) {
    int idx = blockIdx.x * 256 + threadIdx.x;
    int k = blockIdx.y;
    int n = idx >> 4, lane = idx & 15;
    int b = batch[n];
    float4 v = *((const float4*)(g_h1 + (size_t)k * NN * HH + (size_t)n * HH) + lane);
    red_add_f4(((float4*)(g_poolS + ((size_t)k * NB_BATCH + b) * HH)) + lane, v);
}
__global__ __launch_bounds__(256) void cnt_kernel(const int* __restrict__ batch) {
    int idx = blockIdx.x * 256 + threadIdx.x;
    if (idx < NN) atomicAdd(&g_cnt[batch[idx]], 1);
}

// ---------------- finalize ----------------
__global__ __launch_bounds__(64) void finalize_kernel(
    const float* __restrict__ clfW, const float* __restrict__ clfb,
    float* __restrict__ out_logits, float* __restrict__ out_hstab,
    float* __restrict__ out_horig)
{
    int b = blockIdx.x, t = threadIdx.x;
    __shared__ float hs[64];
    float inv = 1.0f / fmaxf((float)g_cnt[b], 1.0f);
    out_horig[b * HH + t] = g_poolZ[b * HH + t] * inv;
    for (int k = 0; k < KK; k++) {
        float v = g_poolS[((size_t)k * NB_BATCH + b) * HH + t] * inv;
        out_hstab[((size_t)b * KK + k) * HH + t] = v;
        hs[t] = v;
        __syncthreads();
        if (t < CC) {
            float sacc = clfb[k * CC + t];
            #pragma unroll 8
            for (int h2 = 0; h2 < HH; h2++)
                sacc += hs[h2] * clfW[((size_t)k * HH + h2) * CC + t];
            out_logits[((size_t)b * KK + k) * CC + t] = sacc;
        }
        __syncthreads();
    }
}

// ---------------- host launch ----------------
extern "C" void kernel_launch(void* const* d_in, const int* in_sizes, int n_in,
                              void* d_out, int out_size)
{
    const float* x     = (const float*)d_in[0];
    const int*   ei    = (const int*)d_in[1];
    const int*   batch = (const int*)d_in[2];
    const float* ceW1  = (const float*)d_in[3];
    const float* ceb1  = (const float*)d_in[4];
    const float* ceW2  = (const float*)d_in[5];
    const float* ceb2  = (const float*)d_in[6];
    const float* ceeps = (const float*)d_in[7];
    const float* clW1  = (const float*)d_in[8];
    const float* clb1  = (const float*)d_in[9];
    const float* clW2  = (const float*)d_in[10];
    const float* clb2  = (const float*)d_in[11];
    const float* cleps = (const float*)d_in[12];
    const float* nmW1  = (const float*)d_in[13];
    const float* nmb1  = (const float*)d_in[14];
    const float* nmW2  = (const float*)d_in[15];
    const float* nmb2  = (const float*)d_in[16];
    const float* emW1  = (const float*)d_in[17];
    const float* emb1  = (const float*)d_in[18];
    const float* emW2  = (const float*)d_in[19];
    const float* emb2  = (const float*)d_in[20];
    const float* fmW1  = (const float*)d_in[21];
    const float* fmb1  = (const float*)d_in[22];
    const float* fmW2  = (const float*)d_in[23];
    const float* fmb2  = (const float*)d_in[24];
    const float* clfW  = (const float*)d_in[25];
    const float* clfb  = (const float*)d_in[26];

    const int* src = ei;
    const int* dst = ei + EE;

    float* Z_p;     cudaGetSymbolAddress((void**)&Z_p, g_Z);
    float* h0_p;    cudaGetSymbolAddress((void**)&h0_p, g_h0);
    float* h1_p;    cudaGetSymbolAddress((void**)&h1_p, g_h1);
    float* ew_p;    cudaGetSymbolAddress((void**)&ew_p, g_ew);
    float* poolZ_p; cudaGetSymbolAddress((void**)&poolZ_p, g_poolZ);
    float* poolS_p; cudaGetSymbolAddress((void**)&poolS_p, g_poolS);
    int*   cnt_p;   cudaGetSymbolAddress((void**)&cnt_p, g_cnt);
    int*   deg_p;   cudaGetSymbolAddress((void**)&deg_p, g_deg);
    int*   fill_p;  cudaGetSymbolAddress((void**)&fill_p, g_fill);

    float* out        = (float*)d_out;
    float* out_logits = out;
    float* out_hstab  = out_logits + NB_BATCH * KK * CC;
    float* out_horig  = out_hstab + NB_BATCH * KK * HH;
    float* out_nm     = out_horig + NB_BATCH * HH;
    float* out_em     = out_nm + (size_t)NN * KK;
    float* out_fm     = out_em + (size_t)EE * KK;

    const int GB = (NN + 63) / 64;
    const int EG = (EE + 255) / 256;
    const int EDGE_GRID = (EE * 16) / 256;
    const int POOL_GRID = (NN * 16) / 256;

    // ---- CSR build ----
    cudaMemsetAsync(deg_p, 0, NN * sizeof(int));
    cudaMemsetAsync(fill_p, 0, NN * sizeof(int));
    hist_kernel<<<EG, 256>>>(dst);
    scan_kernel<<<1, 1024>>>();
    fill_kernel<<<EG, 256>>>(src, dst);

    // ---- causal encoder GIN (3 layers) ----
    ginfused_kernel<<<dim3(GB, 1), 256>>>(x, h0_p, nullptr, ceeps, 0,
                                          ceW1, ceb1, ceW2, ceb2);
    ginfused_kernel<<<dim3(GB, 1), 256>>>(h0_p, h1_p, nullptr, ceeps, 1,
                                          ceW1 + 4096, ceb1 + 64, ceW2 + 4096, ceb2 + 64);
    ginfused_kernel<<<dim3(GB, 1), 256>>>(h1_p, Z_p, nullptr, ceeps, 2,
                                          ceW1 + 8192, ceb1 + 128, ceW2 + 8192, ceb2 + 128);

    // ---- masks ----
    mask_kernel<<<dim3(GB, KK), 256>>>(Z_p, x, nmW1, nmb1, nmW2, nmb2,
                                       emW1, fmW1, fmb1, fmW2, fmb2,
                                       out_nm, out_fm);
    edge_mask_kernel<<<dim3(EDGE_GRID, KK), 256>>>(src, dst, emb1, emW2, emb2, out_em);

    // ---- classifier GIN (3 layers, all K) ----
    ginfused_kernel<<<dim3(GB, KK), 256>>>(h0_p, h1_p, ew_p, cleps, 0,
                                           clW1, clb1, clW2, clb2);
    ginfused_kernel<<<dim3(GB, KK), 256>>>(h1_p, h0_p, ew_p, cleps, 1,
                                           clW1 + 4096, clb1 + 64, clW2 + 4096, clb2 + 64);
    ginfused_kernel<<<dim3(GB, KK), 256>>>(h0_p, h1_p, ew_p, cleps, 2,
                                           clW1 + 8192, clb1 + 128, clW2 + 8192, clb2 + 128);

    // ---- pooling + finalize ----
    cudaMemsetAsync(cnt_p, 0, NB_BATCH * sizeof(int));
    cudaMemsetAsync(poolZ_p, 0, (size_t)NB_BATCH * HH * sizeof(float));
    cudaMemsetAsync(poolS_p, 0, (size_t)KK * NB_BATCH * HH * sizeof(float));
    cnt_kernel<<<(NN + 255) / 256, 256>>>(batch);
    poolZ_kernel<<<POOL_GRID, 256>>>(batch);
    poolS_kernel<<<dim3(POOL_GRID, KK), 256>>>(batch);
    finalize_kernel<<<NB_BATCH, 64>>>(clfW, clfb, out_logits, out_hstab, out_horig);
}